// round 16
// baseline (speedup 1.0000x reference)
#include <cuda_runtime.h>

// BallPredictorGNN — sparse dependency cone + linear-GAT factorization.
// 2 kernels:
//   k_scan: prep was/wad || scan1 (dst==ball) -> grid barrier -> scan2 (L2-hot)
//   k_agg1: per-need1-node; x-rows staged to smem per 32-edge chunk;
//           warp-parallel softmax; last block runs final + state reset.
// R16 fix: shared union must be 16-byte aligned for float4 staging loads.

#define NMAX      20480
#define FIN       128
#define H1C       256
#define C2        64
#define SRCA_CAP  1024
#define EB_CAP    65536
#define LIST_CAP  4096
#define DEG_CAP   512
#define CHUNK     32
#define AGG_GRID  64
#define SCAN_BLK  296

__device__ int   g_need1[NMAX];
__device__ int   g_cntA, g_cntB, g_cnt1, g_done, g_barc;
__device__ int   g_srcA[SRCA_CAP];
__device__ int   g_srcB[EB_CAP];
__device__ int   g_dstB[EB_CAP];
__device__ int   g_list1[LIST_CAP];
__device__ float g_was[FIN * 4];         // [f*4+h]
__device__ float g_wad[FIN * 4];
__device__ float g_g2[(size_t)NMAX * C2];
__device__ float g_as2[NMAX], g_ad2[NMAX];

__device__ __forceinline__ void mark_need1(int v) {
    if (atomicExch(&g_need1[v], 1) == 0) {
        int p = atomicAdd(&g_cnt1, 1);
        if (p < LIST_CAP) g_list1[p] = v;
    }
}

__device__ __forceinline__ void p1_hit(const int* ei, int N, int idx) {
    int src = ei[idx];
    if ((unsigned)src >= (unsigned)N) return;
    int p = atomicAdd(&g_cntA, 1);
    if (p < SRCA_CAP) g_srcA[p] = src;
    mark_need1(src);
}

__device__ __forceinline__ void p2_hit(const int* ei, int N, int idx, int dst) {
    if ((unsigned)dst >= (unsigned)N) return;
    if (g_need1[dst]) {
        int src = ei[idx];
        if ((unsigned)src >= (unsigned)N) return;
        int p = atomicAdd(&g_cntB, 1);
        if (p < EB_CAP) { g_srcB[p] = src; g_dstB[p] = dst; }
    }
}

__global__ void __launch_bounds__(256, 4)
k_scan(const int* __restrict__ ei, int E, int ball, int N,
       const float* __restrict__ W1,
       const float* __restrict__ a_src1, const float* __restrict__ a_dst1) {
    const int b = blockIdx.x, t = threadIdx.x, NB = gridDim.x;
    const int w = t >> 5, l = t & 31;
    const int nq = (E + 3) >> 2;
    const int* dcol = ei + E;

    if (b == 0 && t == 0) mark_need1(ball);

    if (b < 8) {        // prep: was/wad = W1 @ a_{src,dst}1, latency-flat
        __shared__ float s_red[16 * 16];
        const float as = a_src1[t];
        const float ad = a_dst1[t];
        float wv[16];
#pragma unroll
        for (int i = 0; i < 16; i++)
            wv[i] = W1[(b * 16 + i) * H1C + t];
        float ps[16], pd[16];
#pragma unroll
        for (int i = 0; i < 16; i++) { ps[i] = wv[i] * as; pd[i] = wv[i] * ad; }
#pragma unroll
        for (int o = 16; o; o >>= 1)
#pragma unroll
            for (int i = 0; i < 16; i++) {
                ps[i] += __shfl_down_sync(~0u, ps[i], o);
                pd[i] += __shfl_down_sync(~0u, pd[i], o);
            }
        if (l == 0)
#pragma unroll
            for (int i = 0; i < 16; i++) {
                s_red[i * 16 + w] = ps[i];
                s_red[i * 16 + 8 + w] = pd[i];
            }
        __syncthreads();
        if (t < 64) {
            int i = t >> 2, hh = t & 3;
            g_was[(b * 16 + i) * 4 + hh] = s_red[i * 16 + 2 * hh] + s_red[i * 16 + 2 * hh + 1];
            g_wad[(b * 16 + i) * 4 + hh] = s_red[i * 16 + 8 + 2 * hh] + s_red[i * 16 + 8 + 2 * hh + 1];
        }
    } else {
        const int S = (NB - 8) * 256;
        int q = (b - 8) * 256 + t;
        for (; q + S < nq; q += 2 * S) {
            int4 v0 = *reinterpret_cast<const int4*>(dcol + 4 * q);
            int4 v1 = *reinterpret_cast<const int4*>(dcol + 4 * (q + S));
            if (v0.x == ball) p1_hit(ei, N, 4 * q + 0);
            if (v0.y == ball) p1_hit(ei, N, 4 * q + 1);
            if (v0.z == ball) p1_hit(ei, N, 4 * q + 2);
            if (v0.w == ball) p1_hit(ei, N, 4 * q + 3);
            if (v1.x == ball) p1_hit(ei, N, 4 * (q + S) + 0);
            if (v1.y == ball) p1_hit(ei, N, 4 * (q + S) + 1);
            if (v1.z == ball) p1_hit(ei, N, 4 * (q + S) + 2);
            if (v1.w == ball) p1_hit(ei, N, 4 * (q + S) + 3);
        }
        for (; q < nq; q += S) {
            int base = q * 4;
            int d[4];
            if (base + 4 <= E) {
                int4 v = *reinterpret_cast<const int4*>(dcol + base);
                d[0] = v.x; d[1] = v.y; d[2] = v.z; d[3] = v.w;
            } else {
                for (int k = 0; k < 4; k++) d[k] = (base + k < E) ? dcol[base + k] : -1;
            }
#pragma unroll
            for (int k = 0; k < 4; k++) if (d[k] == ball) p1_hit(ei, N, base + k);
        }
    }

    // grid barrier (304 blocks co-resident per launch_bounds)
    __syncthreads();
    if (t == 0) {
        __threadfence();
        atomicAdd(&g_barc, 1);
        while (*(volatile int*)&g_barc < NB) __nanosleep(128);
        __threadfence();
    }
    __syncthreads();

    // scan2 — dst column L2-hot
    {
        const int S = NB * 256;
        int q = b * 256 + t;
        for (; q + S < nq; q += 2 * S) {
            int4 v0 = *reinterpret_cast<const int4*>(dcol + 4 * q);
            int4 v1 = *reinterpret_cast<const int4*>(dcol + 4 * (q + S));
            p2_hit(ei, N, 4 * q + 0, v0.x);        p2_hit(ei, N, 4 * q + 1, v0.y);
            p2_hit(ei, N, 4 * q + 2, v0.z);        p2_hit(ei, N, 4 * q + 3, v0.w);
            p2_hit(ei, N, 4 * (q + S) + 0, v1.x);  p2_hit(ei, N, 4 * (q + S) + 1, v1.y);
            p2_hit(ei, N, 4 * (q + S) + 2, v1.z);  p2_hit(ei, N, 4 * (q + S) + 3, v1.w);
        }
        for (; q < nq; q += S) {
            int base = q * 4;
            int d[4];
            if (base + 4 <= E) {
                int4 v = *reinterpret_cast<const int4*>(dcol + base);
                d[0] = v.x; d[1] = v.y; d[2] = v.z; d[3] = v.w;
            } else {
                for (int k = 0; k < 4; k++) d[k] = (base + k < E) ? dcol[base + k] : -1;
            }
#pragma unroll
            for (int k = 0; k < 4; k++) p2_hit(ei, N, base + k, d[k]);
        }
    }
}

// Shared-memory overlay: agg-phase and final-phase buffers are disjoint in time.
// MUST be 16-byte aligned: xs is accessed via float4.
struct __align__(16) AggShm {
    int   src[DEG_CAP];        // 2048 B
    float e[DEG_CAP * 4];      // 8192 B  -> xs at 10240 (16-mult)
    float xs[CHUNK * FIN];     // 16384 B staged x rows
    float xv[FIN];
    float xagg[4 * FIN];
    float r1[H1C];
    float g2[C2];
    float adv[4], inv[4];
    int   cnt;
};
struct __align__(16) FinShm {
    int   idx[SRCA_CAP + 1];
    float w[SRCA_CAP + 1];
    float o[C2];
    float p2[8 * 32];
    float z[32];
};
union __align__(16) Shm { AggShm a; FinShm f; };

__global__ void k_agg1(const float* __restrict__ x, const float* __restrict__ W1,
                       const float* __restrict__ b1, const float* __restrict__ W2,
                       const float* __restrict__ a_src2, const float* __restrict__ a_dst2,
                       const float* __restrict__ b2,
                       const float* __restrict__ fc1_w, const float* __restrict__ fc1_b,
                       const float* __restrict__ fc2_w, const float* __restrict__ fc2_b,
                       float* __restrict__ out, int ball) {
    __shared__ float s_was[FIN * 4];
    __shared__ float s_wad[FIN * 4];
    __shared__ float s_fc1[C2 * 32];
    __shared__ float s_part[4 * C2];
    __shared__ float s_red[16];
    __shared__ int   s_last;
    __shared__ Shm   u;
    const int t = threadIdx.x, w = t >> 5, l = t & 31, b = blockIdx.x;
    const int n1 = min(g_cnt1, LIST_CAP);
    const int cb = min(g_cntB, EB_CAP);

    for (int i = t; i < C2 * 32; i += 256) s_fc1[i] = fc1_w[i];

    if (b < n1) {
        for (int i = t; i < FIN * 4; i += 256) { s_was[i] = g_was[i]; s_wad[i] = g_wad[i]; }
        for (int it = b; it < n1; it += AGG_GRID) {
            int v = g_list1[it];
            if (t == 0) u.a.cnt = 0;
            if (t < FIN) u.a.xv[t] = x[(size_t)v * FIN + t];
            __syncthreads();
            // gather in-edges (int4 over dstB)
            for (int base = t * 4; base < cb; base += 1024) {
                if (base + 4 <= cb) {
                    int4 dv = *reinterpret_cast<const int4*>(g_dstB + base);
                    if (dv.x == v) { int p = atomicAdd(&u.a.cnt, 1); if (p < DEG_CAP - 1) u.a.src[p] = g_srcB[base + 0]; }
                    if (dv.y == v) { int p = atomicAdd(&u.a.cnt, 1); if (p < DEG_CAP - 1) u.a.src[p] = g_srcB[base + 1]; }
                    if (dv.z == v) { int p = atomicAdd(&u.a.cnt, 1); if (p < DEG_CAP - 1) u.a.src[p] = g_srcB[base + 2]; }
                    if (dv.w == v) { int p = atomicAdd(&u.a.cnt, 1); if (p < DEG_CAP - 1) u.a.src[p] = g_srcB[base + 3]; }
                } else {
                    for (int j = base; j < cb; j++)
                        if (g_dstB[j] == v) { int p = atomicAdd(&u.a.cnt, 1); if (p < DEG_CAP - 1) u.a.src[p] = g_srcB[j]; }
                }
            }
            __syncthreads();
            if (t == 0) {
                int p = min(u.a.cnt, DEG_CAP - 1);
                u.a.src[p] = v;               // appended self-loop (ref order)
                u.a.cnt = p + 1;
            }
            if (w < 4) {                      // dst logits: x[v].wad[:,h]
                float p = 0.f;
                for (int f = l; f < FIN; f += 32) p += u.a.xv[f] * s_wad[f * 4 + w];
#pragma unroll
                for (int o = 16; o; o >>= 1) p += __shfl_down_sync(~0u, p, o);
                if (l == 0) u.a.adv[w] = p;
            }
            __syncthreads();
            const int n = u.a.cnt;
            const int nch = (n + CHUNK - 1) / CHUNK;
            // ---- logits: stage 32 x-rows to smem per chunk, warp per edge ----
            for (int c0 = 0; c0 < n; c0 += CHUNK) {
                const int m = min(CHUNK, n - c0);
                {   // stage: 8 threads per row, 4 float4 each (coalesced)
                    int r = t >> 3, p = t & 7;
                    if (r < m) {
                        const float4* xr = reinterpret_cast<const float4*>(
                                               x + (size_t)u.a.src[c0 + r] * FIN);
                        float4* dst = reinterpret_cast<float4*>(u.a.xs + r * FIN);
#pragma unroll
                        for (int k = 0; k < 4; k++) dst[p * 4 + k] = xr[p * 4 + k];
                    }
                }
                __syncthreads();
                for (int j = w; j < m; j += 8) {
                    const float4 xv4 = reinterpret_cast<const float4*>(u.a.xs + j * FIN)[l];
                    float ph0 = 0.f, ph1 = 0.f, ph2 = 0.f, ph3 = 0.f;
                    const float xsv[4] = {xv4.x, xv4.y, xv4.z, xv4.w};
#pragma unroll
                    for (int k = 0; k < 4; k++) {
                        int f = 4 * l + k;
                        ph0 += xsv[k] * s_was[f * 4 + 0];
                        ph1 += xsv[k] * s_was[f * 4 + 1];
                        ph2 += xsv[k] * s_was[f * 4 + 2];
                        ph3 += xsv[k] * s_was[f * 4 + 3];
                    }
#pragma unroll
                    for (int o = 16; o; o >>= 1) {
                        ph0 += __shfl_down_sync(~0u, ph0, o);
                        ph1 += __shfl_down_sync(~0u, ph1, o);
                        ph2 += __shfl_down_sync(~0u, ph2, o);
                        ph3 += __shfl_down_sync(~0u, ph3, o);
                    }
                    if (l == 0) {
                        int jj = c0 + j;
                        float e0 = ph0 + u.a.adv[0], e1 = ph1 + u.a.adv[1];
                        float e2 = ph2 + u.a.adv[2], e3 = ph3 + u.a.adv[3];
                        u.a.e[jj * 4 + 0] = (e0 > 0.f) ? e0 : 0.2f * e0;  // leaky
                        u.a.e[jj * 4 + 1] = (e1 > 0.f) ? e1 : 0.2f * e1;
                        u.a.e[jj * 4 + 2] = (e2 > 0.f) ? e2 : 0.2f * e2;
                        u.a.e[jj * 4 + 3] = (e3 > 0.f) ? e3 : 0.2f * e3;
                    }
                }
                __syncthreads();
            }
            // ---- softmax: warp per head, lanes over edges ----
            if (w < 4) {
                float mx = -1e30f;
                for (int j = l; j < n; j += 32) mx = fmaxf(mx, u.a.e[j * 4 + w]);
#pragma unroll
                for (int o = 16; o; o >>= 1) mx = fmaxf(mx, __shfl_xor_sync(~0u, mx, o));
                float s = 0.f;
                for (int j = l; j < n; j += 32) {
                    float ww = expf(u.a.e[j * 4 + w] - mx);
                    u.a.e[j * 4 + w] = ww; s += ww;
                }
#pragma unroll
                for (int o = 16; o; o >>= 1) s += __shfl_xor_sync(~0u, s, o);
                if (l == 0) u.a.inv[w] = 1.f / (s + 1e-16f);
            }
            __syncthreads();
            // ---- xagg: chunked from smem (re-stage only if multi-chunk) ----
            float a0 = 0.f, a1 = 0.f, a2 = 0.f, a3 = 0.f;
            for (int c0 = 0; c0 < n; c0 += CHUNK) {
                const int m = min(CHUNK, n - c0);
                if (nch > 1) {
                    int r = t >> 3, p = t & 7;
                    if (r < m) {
                        const float4* xr = reinterpret_cast<const float4*>(
                                               x + (size_t)u.a.src[c0 + r] * FIN);
                        float4* dst = reinterpret_cast<float4*>(u.a.xs + r * FIN);
#pragma unroll
                        for (int k = 0; k < 4; k++) dst[p * 4 + k] = xr[p * 4 + k];
                    }
                    __syncthreads();
                }
                if (t < FIN) {
                    for (int j = 0; j < m; j++) {
                        float xv = u.a.xs[j * FIN + t];
                        int jj = c0 + j;
                        a0 += u.a.e[jj * 4 + 0] * xv;
                        a1 += u.a.e[jj * 4 + 1] * xv;
                        a2 += u.a.e[jj * 4 + 2] * xv;
                        a3 += u.a.e[jj * 4 + 3] * xv;
                    }
                }
                if (nch > 1) __syncthreads();
            }
            if (t < FIN) {
                u.a.xagg[0 * FIN + t] = a0 * u.a.inv[0];
                u.a.xagg[1 * FIN + t] = a1 * u.a.inv[1];
                u.a.xagg[2 * FIN + t] = a2 * u.a.inv[2];
                u.a.xagg[3 * FIN + t] = a3 * u.a.inv[3];
            }
            __syncthreads();
            {                                 // @W1 -> r1
                const int h = t >> 6;
                float acc = 0.f;
#pragma unroll 32
                for (int f = 0; f < FIN; f++)
                    acc += u.a.xagg[h * FIN + f] * W1[f * H1C + t];
                u.a.r1[t] = fmaxf(acc + b1[t], 0.f);
            }
            __syncthreads();
            {                                 // g2 = r1 @ W2
                const int c = t & 63, q = t >> 6;
                float p = 0.f;
#pragma unroll 32
                for (int k = q * 64; k < q * 64 + 64; k++)
                    p += u.a.r1[k] * W2[k * C2 + c];
                s_part[q * C2 + c] = p;
            }
            __syncthreads();
            if (t < C2) {
                float g = s_part[t] + s_part[C2 + t] + s_part[2 * C2 + t] + s_part[3 * C2 + t];
                u.a.g2[t] = g;
                g_g2[(size_t)v * C2 + t] = g;
            }
            __syncthreads();
            if (w < 2) {                      // layer-2 logits
                const float* av = w ? a_dst2 : a_src2;
                float p = u.a.g2[l] * av[l] + u.a.g2[l + 32] * av[l + 32];
#pragma unroll
                for (int o = 16; o; o >>= 1) p += __shfl_down_sync(~0u, p, o);
                if (l == 0) { if (w) g_ad2[v] = p; else g_as2[v] = p; }
            }
            __syncthreads();
        }
    }

    // ---- done counter: last-finishing block runs the final phase ----
    __syncthreads();
    if (t == 0) {
        __threadfence();
        s_last = (atomicAdd(&g_done, 1) + 1 == gridDim.x) ? 1 : 0;
        if (s_last) __threadfence();
    }
    __syncthreads();
    if (!s_last) return;

    // ================= final (one block, overlay u.f) =====================
    const int nA = min(g_cntA, SRCA_CAP);
    const int cnt = nA + 1;
    for (int j = t; j < cnt; j += 256) u.f.idx[j] = (j < nA) ? g_srcA[j] : ball;
    __syncthreads();
    const float adv = g_ad2[ball];
    for (int j = t; j < cnt; j += 256) {
        float e = g_as2[u.f.idx[j]] + adv;
        u.f.w[j] = (e > 0.f) ? e : 0.2f * e;
    }
    __syncthreads();
    float lm = -1e30f;
    for (int j = t; j < cnt; j += 256) lm = fmaxf(lm, u.f.w[j]);
#pragma unroll
    for (int o = 16; o; o >>= 1) lm = fmaxf(lm, __shfl_down_sync(~0u, lm, o));
    if (l == 0) s_red[w] = lm;
    __syncthreads();
    if (t < 8) {
        float v = s_red[t];
#pragma unroll
        for (int o = 4; o; o >>= 1) v = fmaxf(v, __shfl_down_sync(0xffu, v, o));
        if (t == 0) s_red[0] = v;
    }
    __syncthreads();
    const float m = s_red[0];
    float ls = 0.f;
    for (int j = t; j < cnt; j += 256) { float ww = expf(u.f.w[j] - m); u.f.w[j] = ww; ls += ww; }
#pragma unroll
    for (int o = 16; o; o >>= 1) ls += __shfl_down_sync(~0u, ls, o);
    if (l == 0) s_red[8 + w] = ls;
    __syncthreads();
    if (t < 8) {
        float v = s_red[8 + t];
#pragma unroll
        for (int o = 4; o; o >>= 1) v += __shfl_down_sync(0xffu, v, o);
        if (t == 0) s_red[8] = v;
    }
    __syncthreads();
    const float sinv = 1.f / (s_red[8] + 1e-16f);
    {   // aggregate g2 (rows L2-hot)
        const int c = t & 63, q = t >> 6;
        float acc = 0.f;
        for (int j = q; j < cnt; j += 4)
            acc += u.f.w[j] * g_g2[(size_t)u.f.idx[j] * C2 + c];
        s_part[q * C2 + c] = acc;
    }
    __syncthreads();
    if (t < C2) {
        float o = (s_part[t] + s_part[C2 + t] + s_part[2 * C2 + t] + s_part[3 * C2 + t])
                  * sinv + b2[t];
        u.f.o[t] = fmaxf(o, 0.f);
    }
    __syncthreads();
    {   // fc1 (weights in smem)
        const int o = t & 31, q = t >> 5;
        float p = 0.f;
#pragma unroll
        for (int k = q * 8; k < q * 8 + 8; k++) p += u.f.o[k] * s_fc1[k * 32 + o];
        u.f.p2[q * 32 + o] = p;
    }
    __syncthreads();
    if (t < 32) {
        float a = fc1_b[t];
#pragma unroll
        for (int q = 0; q < 8; q++) a += u.f.p2[q * 32 + t];
        u.f.z[t] = fmaxf(a, 0.f);
    }
    __syncthreads();
    if (t < 2) {
        float a = fc2_b[t];
        for (int k = 0; k < 32; k++) a += u.f.z[k] * fc2_w[k * 2 + t];
        out[t] = a;
    }
    // ---- reset state for next graph replay ----
    __syncthreads();
    const int n1r = min(g_cnt1, LIST_CAP);
    for (int i = t; i < n1r; i += 256) g_need1[g_list1[i]] = 0;
    if (t == 0) { g_cntA = 0; g_cntB = 0; g_cnt1 = 0; g_done = 0; g_barc = 0; }
}

extern "C" void kernel_launch(void* const* d_in, const int* in_sizes, int n_in,
                              void* d_out, int out_size) {
    const float* x      = (const float*)d_in[0];
    const int*   ei     = (const int*)d_in[1];   // int32 (JAX x64-disabled)
    const float* W1     = (const float*)d_in[2];
    const float* a_src1 = (const float*)d_in[3];
    const float* a_dst1 = (const float*)d_in[4];
    const float* b1     = (const float*)d_in[5];
    const float* W2     = (const float*)d_in[6];
    const float* a_src2 = (const float*)d_in[7];
    const float* a_dst2 = (const float*)d_in[8];
    const float* b2     = (const float*)d_in[9];
    const float* fc1_w  = (const float*)d_in[10];
    const float* fc1_b  = (const float*)d_in[11];
    const float* fc2_w  = (const float*)d_in[12];
    const float* fc2_b  = (const float*)d_in[13];

    int N = in_sizes[0] / FIN;   // 20000
    int E = in_sizes[1] / 2;     // 640000
    int ball = N - 1;

    k_scan<<<8 + SCAN_BLK, 256>>>(ei, E, ball, N, W1, a_src1, a_dst1);
    k_agg1<<<AGG_GRID, 256>>>(x, W1, b1, W2, a_src2, a_dst2,
                              b2, fc1_w, fc1_b, fc2_w, fc2_b,
                              (float*)d_out, ball);
}

// round 17
// speedup vs baseline: 1.0322x; 1.0322x over previous
#include <cuda_runtime.h>

// BallPredictorGNN — sparse dependency cone + linear-GAT factorization.
// 2 kernels (R14 structure):
//   k_scan: prep was/wad || scan1 (dst==ball) -> grid barrier -> scan2 (L2-hot)
//   k_agg1: per-need1-node aggregate/project; last block runs final + reset.
// R17: warp-parallel softmax; xagg split across 2 thread-halves (256 threads,
// half the dependent-load chain); final g2 aggregate 4-way unrolled.

#define NMAX      20480
#define FIN       128
#define H1C       256
#define C2        64
#define SRCA_CAP  1024
#define EB_CAP    65536
#define LIST_CAP  4096
#define DEG_CAP   512
#define AGG_GRID  64
#define SCAN_BLK  296

__device__ int   g_need1[NMAX];
__device__ int   g_cntA, g_cntB, g_cnt1, g_done, g_barc;
__device__ int   g_srcA[SRCA_CAP];
__device__ int   g_srcB[EB_CAP];
__device__ int   g_dstB[EB_CAP];
__device__ int   g_list1[LIST_CAP];
__device__ float g_was[FIN * 4];         // [f*4+h]
__device__ float g_wad[FIN * 4];
__device__ float g_g2[(size_t)NMAX * C2];
__device__ float g_as2[NMAX], g_ad2[NMAX];

__device__ __forceinline__ void mark_need1(int v) {
    if (atomicExch(&g_need1[v], 1) == 0) {
        int p = atomicAdd(&g_cnt1, 1);
        if (p < LIST_CAP) g_list1[p] = v;
    }
}

__device__ __forceinline__ void p1_hit(const int* ei, int N, int idx) {
    int src = ei[idx];
    if ((unsigned)src >= (unsigned)N) return;
    int p = atomicAdd(&g_cntA, 1);
    if (p < SRCA_CAP) g_srcA[p] = src;
    mark_need1(src);
}

__device__ __forceinline__ void p2_hit(const int* ei, int N, int idx, int dst) {
    if ((unsigned)dst >= (unsigned)N) return;
    if (g_need1[dst]) {
        int src = ei[idx];
        if ((unsigned)src >= (unsigned)N) return;
        int p = atomicAdd(&g_cntB, 1);
        if (p < EB_CAP) { g_srcB[p] = src; g_dstB[p] = dst; }
    }
}

__global__ void __launch_bounds__(256, 4)
k_scan(const int* __restrict__ ei, int E, int ball, int N,
       const float* __restrict__ W1,
       const float* __restrict__ a_src1, const float* __restrict__ a_dst1) {
    const int b = blockIdx.x, t = threadIdx.x, NB = gridDim.x;
    const int w = t >> 5, l = t & 31;
    const int nq = (E + 3) >> 2;
    const int* dcol = ei + E;

    if (b == 0 && t == 0) mark_need1(ball);

    if (b < 8) {        // prep: was/wad = W1 @ a_{src,dst}1, latency-flat
        __shared__ float s_red[16 * 16];
        const float as = a_src1[t];
        const float ad = a_dst1[t];
        float wv[16];
#pragma unroll
        for (int i = 0; i < 16; i++)
            wv[i] = W1[(b * 16 + i) * H1C + t];
        float ps[16], pd[16];
#pragma unroll
        for (int i = 0; i < 16; i++) { ps[i] = wv[i] * as; pd[i] = wv[i] * ad; }
#pragma unroll
        for (int o = 16; o; o >>= 1)
#pragma unroll
            for (int i = 0; i < 16; i++) {
                ps[i] += __shfl_down_sync(~0u, ps[i], o);
                pd[i] += __shfl_down_sync(~0u, pd[i], o);
            }
        if (l == 0)
#pragma unroll
            for (int i = 0; i < 16; i++) {
                s_red[i * 16 + w] = ps[i];
                s_red[i * 16 + 8 + w] = pd[i];
            }
        __syncthreads();
        if (t < 64) {
            int i = t >> 2, hh = t & 3;
            g_was[(b * 16 + i) * 4 + hh] = s_red[i * 16 + 2 * hh] + s_red[i * 16 + 2 * hh + 1];
            g_wad[(b * 16 + i) * 4 + hh] = s_red[i * 16 + 8 + 2 * hh] + s_red[i * 16 + 8 + 2 * hh + 1];
        }
    } else {
        const int S = (NB - 8) * 256;
        int q = (b - 8) * 256 + t;
        for (; q + S < nq; q += 2 * S) {
            int4 v0 = *reinterpret_cast<const int4*>(dcol + 4 * q);
            int4 v1 = *reinterpret_cast<const int4*>(dcol + 4 * (q + S));
            if (v0.x == ball) p1_hit(ei, N, 4 * q + 0);
            if (v0.y == ball) p1_hit(ei, N, 4 * q + 1);
            if (v0.z == ball) p1_hit(ei, N, 4 * q + 2);
            if (v0.w == ball) p1_hit(ei, N, 4 * q + 3);
            if (v1.x == ball) p1_hit(ei, N, 4 * (q + S) + 0);
            if (v1.y == ball) p1_hit(ei, N, 4 * (q + S) + 1);
            if (v1.z == ball) p1_hit(ei, N, 4 * (q + S) + 2);
            if (v1.w == ball) p1_hit(ei, N, 4 * (q + S) + 3);
        }
        for (; q < nq; q += S) {
            int base = q * 4;
            int d[4];
            if (base + 4 <= E) {
                int4 v = *reinterpret_cast<const int4*>(dcol + base);
                d[0] = v.x; d[1] = v.y; d[2] = v.z; d[3] = v.w;
            } else {
                for (int k = 0; k < 4; k++) d[k] = (base + k < E) ? dcol[base + k] : -1;
            }
#pragma unroll
            for (int k = 0; k < 4; k++) if (d[k] == ball) p1_hit(ei, N, base + k);
        }
    }

    // grid barrier (304 blocks co-resident per launch_bounds)
    __syncthreads();
    if (t == 0) {
        __threadfence();
        atomicAdd(&g_barc, 1);
        while (*(volatile int*)&g_barc < NB) __nanosleep(128);
        __threadfence();
    }
    __syncthreads();

    // scan2 — dst column L2-hot
    {
        const int S = NB * 256;
        int q = b * 256 + t;
        for (; q + S < nq; q += 2 * S) {
            int4 v0 = *reinterpret_cast<const int4*>(dcol + 4 * q);
            int4 v1 = *reinterpret_cast<const int4*>(dcol + 4 * (q + S));
            p2_hit(ei, N, 4 * q + 0, v0.x);        p2_hit(ei, N, 4 * q + 1, v0.y);
            p2_hit(ei, N, 4 * q + 2, v0.z);        p2_hit(ei, N, 4 * q + 3, v0.w);
            p2_hit(ei, N, 4 * (q + S) + 0, v1.x);  p2_hit(ei, N, 4 * (q + S) + 1, v1.y);
            p2_hit(ei, N, 4 * (q + S) + 2, v1.z);  p2_hit(ei, N, 4 * (q + S) + 3, v1.w);
        }
        for (; q < nq; q += S) {
            int base = q * 4;
            int d[4];
            if (base + 4 <= E) {
                int4 v = *reinterpret_cast<const int4*>(dcol + base);
                d[0] = v.x; d[1] = v.y; d[2] = v.z; d[3] = v.w;
            } else {
                for (int k = 0; k < 4; k++) d[k] = (base + k < E) ? dcol[base + k] : -1;
            }
#pragma unroll
            for (int k = 0; k < 4; k++) p2_hit(ei, N, base + k, d[k]);
        }
    }
}

// One block per need1 node; LAST finishing block also runs the final phase.
__global__ void k_agg1(const float* __restrict__ x, const float* __restrict__ W1,
                       const float* __restrict__ b1, const float* __restrict__ W2,
                       const float* __restrict__ a_src2, const float* __restrict__ a_dst2,
                       const float* __restrict__ b2,
                       const float* __restrict__ fc1_w, const float* __restrict__ fc1_b,
                       const float* __restrict__ fc2_w, const float* __restrict__ fc2_b,
                       float* __restrict__ out, int ball) {
    __shared__ float s_was[FIN * 4];
    __shared__ float s_wad[FIN * 4];
    __shared__ int   s_src[DEG_CAP];
    __shared__ float s_e[DEG_CAP * 4];
    __shared__ float s_xv[FIN];
    __shared__ float s_xp[8 * FIN];      // [half*4+h][f] xagg partials
    __shared__ float s_xagg[4 * FIN];
    __shared__ float s_r1[H1C];
    __shared__ float s_part[4 * C2];
    __shared__ float s_g2[C2];
    __shared__ float s_adv[4];
    __shared__ float s_inv[4];
    __shared__ int   s_cnt;
    __shared__ float s_fc1[C2 * 32];
    __shared__ int   s_idx[SRCA_CAP + 1];
    __shared__ float sw[SRCA_CAP + 1];
    __shared__ float s_o[C2];
    __shared__ float s_p2[8 * 32];
    __shared__ float s_z[32];
    __shared__ float s_red[16];
    __shared__ int   s_last;
    const int t = threadIdx.x, w = t >> 5, l = t & 31, b = blockIdx.x;
    const int n1 = min(g_cnt1, LIST_CAP);
    const int cb = min(g_cntB, EB_CAP);

    for (int i = t; i < C2 * 32; i += 256) s_fc1[i] = fc1_w[i];

    if (b < n1) {
        for (int i = t; i < FIN * 4; i += 256) { s_was[i] = g_was[i]; s_wad[i] = g_wad[i]; }
        for (int it = b; it < n1; it += AGG_GRID) {
            int v = g_list1[it];
            if (t == 0) s_cnt = 0;
            if (t < FIN) s_xv[t] = x[(size_t)v * FIN + t];
            __syncthreads();
            for (int base = t * 4; base < cb; base += 1024) {
                if (base + 4 <= cb) {
                    int4 dv = *reinterpret_cast<const int4*>(g_dstB + base);
                    if (dv.x == v) { int p = atomicAdd(&s_cnt, 1); if (p < DEG_CAP - 1) s_src[p] = g_srcB[base + 0]; }
                    if (dv.y == v) { int p = atomicAdd(&s_cnt, 1); if (p < DEG_CAP - 1) s_src[p] = g_srcB[base + 1]; }
                    if (dv.z == v) { int p = atomicAdd(&s_cnt, 1); if (p < DEG_CAP - 1) s_src[p] = g_srcB[base + 2]; }
                    if (dv.w == v) { int p = atomicAdd(&s_cnt, 1); if (p < DEG_CAP - 1) s_src[p] = g_srcB[base + 3]; }
                } else {
                    for (int j = base; j < cb; j++)
                        if (g_dstB[j] == v) { int p = atomicAdd(&s_cnt, 1); if (p < DEG_CAP - 1) s_src[p] = g_srcB[j]; }
                }
            }
            __syncthreads();
            if (t == 0) {
                int p = min(s_cnt, DEG_CAP - 1);
                s_src[p] = v;                 // appended self-loop (ref order)
                s_cnt = p + 1;
            }
            if (w < 4) {                      // dst logits: x[v].wad[:,h]
                float p = 0.f;
                for (int f = l; f < FIN; f += 32) p += s_xv[f] * s_wad[f * 4 + w];
#pragma unroll
                for (int o = 16; o; o >>= 1) p += __shfl_down_sync(~0u, p, o);
                if (l == 0) s_adv[w] = p;
            }
            __syncthreads();
            const int n = s_cnt;
            for (int j = w; j < n; j += 8) {  // src logits, warp per edge
                const float4 xv4 = reinterpret_cast<const float4*>(
                                       x + (size_t)s_src[j] * FIN)[l];
                float ph0 = 0.f, ph1 = 0.f, ph2 = 0.f, ph3 = 0.f;
                const float xs[4] = {xv4.x, xv4.y, xv4.z, xv4.w};
#pragma unroll
                for (int k = 0; k < 4; k++) {
                    int f = 4 * l + k;
                    ph0 += xs[k] * s_was[f * 4 + 0];
                    ph1 += xs[k] * s_was[f * 4 + 1];
                    ph2 += xs[k] * s_was[f * 4 + 2];
                    ph3 += xs[k] * s_was[f * 4 + 3];
                }
#pragma unroll
                for (int o = 16; o; o >>= 1) {
                    ph0 += __shfl_down_sync(~0u, ph0, o);
                    ph1 += __shfl_down_sync(~0u, ph1, o);
                    ph2 += __shfl_down_sync(~0u, ph2, o);
                    ph3 += __shfl_down_sync(~0u, ph3, o);
                }
                if (l == 0) {
                    float e0 = ph0 + s_adv[0], e1 = ph1 + s_adv[1];
                    float e2 = ph2 + s_adv[2], e3 = ph3 + s_adv[3];
                    s_e[j * 4 + 0] = (e0 > 0.f) ? e0 : 0.2f * e0;  // leaky_relu
                    s_e[j * 4 + 1] = (e1 > 0.f) ? e1 : 0.2f * e1;
                    s_e[j * 4 + 2] = (e2 > 0.f) ? e2 : 0.2f * e2;
                    s_e[j * 4 + 3] = (e3 > 0.f) ? e3 : 0.2f * e3;
                }
            }
            __syncthreads();
            if (w < 4) {                      // softmax: warp per head
                float mx = -1e30f;
                for (int j = l; j < n; j += 32) mx = fmaxf(mx, s_e[j * 4 + w]);
#pragma unroll
                for (int o = 16; o; o >>= 1) mx = fmaxf(mx, __shfl_xor_sync(~0u, mx, o));
                float s = 0.f;
                for (int j = l; j < n; j += 32) {
                    float ww = expf(s_e[j * 4 + w] - mx);
                    s_e[j * 4 + w] = ww; s += ww;
                }
#pragma unroll
                for (int o = 16; o; o >>= 1) s += __shfl_xor_sync(~0u, s, o);
                if (l == 0) s_inv[w] = 1.f / (s + 1e-16f);
            }
            __syncthreads();
            {   // xagg: 2 thread-halves over edges, 4-way unrolled each
                const int f = t & 127, half = t >> 7;
                float a0 = 0.f, a1 = 0.f, a2 = 0.f, a3 = 0.f;
                int j = half;
                for (; j + 6 < n; j += 8) {
                    float x0 = x[(size_t)s_src[j + 0] * FIN + f];
                    float x1 = x[(size_t)s_src[j + 2] * FIN + f];
                    float x2 = x[(size_t)s_src[j + 4] * FIN + f];
                    float x3 = x[(size_t)s_src[j + 6] * FIN + f];
                    a0 += s_e[(j+0)*4+0]*x0 + s_e[(j+2)*4+0]*x1 + s_e[(j+4)*4+0]*x2 + s_e[(j+6)*4+0]*x3;
                    a1 += s_e[(j+0)*4+1]*x0 + s_e[(j+2)*4+1]*x1 + s_e[(j+4)*4+1]*x2 + s_e[(j+6)*4+1]*x3;
                    a2 += s_e[(j+0)*4+2]*x0 + s_e[(j+2)*4+2]*x1 + s_e[(j+4)*4+2]*x2 + s_e[(j+6)*4+2]*x3;
                    a3 += s_e[(j+0)*4+3]*x0 + s_e[(j+2)*4+3]*x1 + s_e[(j+4)*4+3]*x2 + s_e[(j+6)*4+3]*x3;
                }
                for (; j < n; j += 2) {
                    float xv = x[(size_t)s_src[j] * FIN + f];
                    a0 += s_e[j*4+0]*xv; a1 += s_e[j*4+1]*xv;
                    a2 += s_e[j*4+2]*xv; a3 += s_e[j*4+3]*xv;
                }
                s_xp[(half * 4 + 0) * FIN + f] = a0;
                s_xp[(half * 4 + 1) * FIN + f] = a1;
                s_xp[(half * 4 + 2) * FIN + f] = a2;
                s_xp[(half * 4 + 3) * FIN + f] = a3;
            }
            __syncthreads();
            if (t < FIN) {
                s_xagg[0 * FIN + t] = (s_xp[0 * FIN + t] + s_xp[4 * FIN + t]) * s_inv[0];
                s_xagg[1 * FIN + t] = (s_xp[1 * FIN + t] + s_xp[5 * FIN + t]) * s_inv[1];
                s_xagg[2 * FIN + t] = (s_xp[2 * FIN + t] + s_xp[6 * FIN + t]) * s_inv[2];
                s_xagg[3 * FIN + t] = (s_xp[3 * FIN + t] + s_xp[7 * FIN + t]) * s_inv[3];
            }
            __syncthreads();
            {                                 // @W1 -> r1
                const int h = t >> 6;
                float acc = 0.f;
#pragma unroll 32
                for (int f = 0; f < FIN; f++)
                    acc += s_xagg[h * FIN + f] * W1[f * H1C + t];
                s_r1[t] = fmaxf(acc + b1[t], 0.f);
            }
            __syncthreads();
            {                                 // g2 = r1 @ W2
                const int c = t & 63, q = t >> 6;
                float p = 0.f;
#pragma unroll 32
                for (int k = q * 64; k < q * 64 + 64; k++)
                    p += s_r1[k] * W2[k * C2 + c];
                s_part[q * C2 + c] = p;
            }
            __syncthreads();
            if (t < C2) {
                float g = s_part[t] + s_part[C2 + t] + s_part[2 * C2 + t] + s_part[3 * C2 + t];
                s_g2[t] = g;
                g_g2[(size_t)v * C2 + t] = g;
            }
            __syncthreads();
            if (w < 2) {                      // layer-2 logits
                const float* av = w ? a_dst2 : a_src2;
                float p = s_g2[l] * av[l] + s_g2[l + 32] * av[l + 32];
#pragma unroll
                for (int o = 16; o; o >>= 1) p += __shfl_down_sync(~0u, p, o);
                if (l == 0) { if (w) g_ad2[v] = p; else g_as2[v] = p; }
            }
            __syncthreads();
        }
    }

    // ---- done counter: last-finishing block runs the final phase ----
    __syncthreads();
    if (t == 0) {
        __threadfence();
        s_last = (atomicAdd(&g_done, 1) + 1 == gridDim.x) ? 1 : 0;
        if (s_last) __threadfence();
    }
    __syncthreads();
    if (!s_last) return;

    // ================= final (one block) ==================================
    const int nA = min(g_cntA, SRCA_CAP);
    const int cnt = nA + 1;
    for (int j = t; j < cnt; j += 256) s_idx[j] = (j < nA) ? g_srcA[j] : ball;
    __syncthreads();
    const float adv = g_ad2[ball];
    for (int j = t; j < cnt; j += 256) {
        float e = g_as2[s_idx[j]] + adv;
        sw[j] = (e > 0.f) ? e : 0.2f * e;
    }
    __syncthreads();
    float lm = -1e30f;
    for (int j = t; j < cnt; j += 256) lm = fmaxf(lm, sw[j]);
#pragma unroll
    for (int o = 16; o; o >>= 1) lm = fmaxf(lm, __shfl_down_sync(~0u, lm, o));
    if (l == 0) s_red[w] = lm;
    __syncthreads();
    if (t < 8) {
        float v = s_red[t];
#pragma unroll
        for (int o = 4; o; o >>= 1) v = fmaxf(v, __shfl_down_sync(0xffu, v, o));
        if (t == 0) s_red[0] = v;
    }
    __syncthreads();
    const float m = s_red[0];
    float ls = 0.f;
    for (int j = t; j < cnt; j += 256) { float ww = expf(sw[j] - m); sw[j] = ww; ls += ww; }
#pragma unroll
    for (int o = 16; o; o >>= 1) ls += __shfl_down_sync(~0u, ls, o);
    if (l == 0) s_red[8 + w] = ls;
    __syncthreads();
    if (t < 8) {
        float v = s_red[8 + t];
#pragma unroll
        for (int o = 4; o; o >>= 1) v += __shfl_down_sync(0xffu, v, o);
        if (t == 0) s_red[8] = v;
    }
    __syncthreads();
    const float sinv = 1.f / (s_red[8] + 1e-16f);
    {   // aggregate g2: quarters over j, 4 independent loads in flight
        const int c = t & 63, q = t >> 6;
        float acc = 0.f;
        int j = q;
        for (; j + 12 < cnt; j += 16) {
            float r0 = g_g2[(size_t)s_idx[j + 0]  * C2 + c];
            float r1 = g_g2[(size_t)s_idx[j + 4]  * C2 + c];
            float r2 = g_g2[(size_t)s_idx[j + 8]  * C2 + c];
            float r3 = g_g2[(size_t)s_idx[j + 12] * C2 + c];
            acc += sw[j]*r0 + sw[j+4]*r1 + sw[j+8]*r2 + sw[j+12]*r3;
        }
        for (; j < cnt; j += 4)
            acc += sw[j] * g_g2[(size_t)s_idx[j] * C2 + c];
        s_part[q * C2 + c] = acc;
    }
    __syncthreads();
    if (t < C2) {
        float o = (s_part[t] + s_part[C2 + t] + s_part[2 * C2 + t] + s_part[3 * C2 + t])
                  * sinv + b2[t];
        s_o[t] = fmaxf(o, 0.f);
    }
    __syncthreads();
    {   // fc1 (weights in smem)
        const int o = t & 31, q = t >> 5;
        float p = 0.f;
#pragma unroll
        for (int k = q * 8; k < q * 8 + 8; k++) p += s_o[k] * s_fc1[k * 32 + o];
        s_p2[q * 32 + o] = p;
    }
    __syncthreads();
    if (t < 32) {
        float a = fc1_b[t];
#pragma unroll
        for (int q = 0; q < 8; q++) a += s_p2[q * 32 + t];
        s_z[t] = fmaxf(a, 0.f);
    }
    __syncthreads();
    if (t < 2) {
        float a = fc2_b[t];
        for (int k = 0; k < 32; k++) a += s_z[k] * fc2_w[k * 2 + t];
        out[t] = a;
    }
    // ---- reset state for next graph replay ----
    __syncthreads();
    const int n1r = min(g_cnt1, LIST_CAP);
    for (int i = t; i < n1r; i += 256) g_need1[g_list1[i]] = 0;
    if (t == 0) { g_cntA = 0; g_cntB = 0; g_cnt1 = 0; g_done = 0; g_barc = 0; }
}

extern "C" void kernel_launch(void* const* d_in, const int* in_sizes, int n_in,
                              void* d_out, int out_size) {
    const float* x      = (const float*)d_in[0];
    const int*   ei     = (const int*)d_in[1];   // int32 (JAX x64-disabled)
    const float* W1     = (const float*)d_in[2];
    const float* a_src1 = (const float*)d_in[3];
    const float* a_dst1 = (const float*)d_in[4];
    const float* b1     = (const float*)d_in[5];
    const float* W2     = (const float*)d_in[6];
    const float* a_src2 = (const float*)d_in[7];
    const float* a_dst2 = (const float*)d_in[8];
    const float* b2     = (const float*)d_in[9];
    const float* fc1_w  = (const float*)d_in[10];
    const float* fc1_b  = (const float*)d_in[11];
    const float* fc2_w  = (const float*)d_in[12];
    const float* fc2_b  = (const float*)d_in[13];

    int N = in_sizes[0] / FIN;   // 20000
    int E = in_sizes[1] / 2;     // 640000
    int ball = N - 1;

    k_scan<<<8 + SCAN_BLK, 256>>>(ei, E, ball, N, W1, a_src1, a_dst1);
    k_agg1<<<AGG_GRID, 256>>>(x, W1, b1, W2, a_src2, a_dst2,
                              b2, fc1_w, fc1_b, fc2_w, fc2_b,
                              (float*)d_out, ball);
}